// round 5
// baseline (speedup 1.0000x reference)
#include <cuda_runtime.h>
#include <cuda_bf16.h>
#include <cstdint>

#define SEQ_L 50
#define DIM 100
#define KPAD 128
#define FFDIM 2048
#define KPRED 100
#define EPS 1e-5f
#define BMAX 16384

typedef __nv_bfloat16 bf16;

// ---------------- scratch (device globals) ---------------------------------
__device__ float g_x [BMAX * DIM];
__device__ float g_ff[BMAX * DIM];
__device__ float g_c [KPAD];
__device__ bf16  g_Mh [KPAD * KPAD],  g_Ml [KPAD * KPAD];
__device__ bf16  g_rech[KPAD * KPAD], g_recl[KPAD * KPAD];
__device__ bf16  g_x1h[BMAX * KPAD],  g_x1l[BMAX * KPAD];
__device__ bf16  g_w1h[FFDIM * KPAD], g_w1l[FFDIM * KPAD];
__device__ bf16  g_hh [(size_t)BMAX * FFDIM], g_hl[(size_t)BMAX * FFDIM];
__device__ bf16  g_w2h[KPAD * FFDIM], g_w2l[KPAD * FFDIM];

// ---------------- helpers ----------------------------------------------------
__device__ __forceinline__ uint32_t smem_u32(const void* p) {
    uint32_t a;
    asm("{ .reg .u64 t; cvta.to.shared.u64 t, %1; cvt.u32.u64 %0, t; }" : "=r"(a) : "l"(p));
    return a;
}
__device__ __forceinline__ void ldsm_x4(uint32_t addr, uint32_t& r0, uint32_t& r1,
                                        uint32_t& r2, uint32_t& r3) {
    asm volatile("ldmatrix.sync.aligned.m8n8.x4.shared.b16 {%0,%1,%2,%3}, [%4];"
                 : "=r"(r0), "=r"(r1), "=r"(r2), "=r"(r3) : "r"(addr));
}
__device__ __forceinline__ void mma_bf16(float* d, const uint32_t* a, const uint32_t* b) {
    asm volatile("mma.sync.aligned.m16n8k16.row.col.f32.bf16.bf16.f32 "
                 "{%0,%1,%2,%3}, {%4,%5,%6,%7}, {%8,%9}, {%0,%1,%2,%3};"
                 : "+f"(d[0]), "+f"(d[1]), "+f"(d[2]), "+f"(d[3])
                 : "r"(a[0]), "r"(a[1]), "r"(a[2]), "r"(a[3]), "r"(b[0]), "r"(b[1]));
}
__device__ __forceinline__ void cp16(uint32_t saddr, const void* g) {
    asm volatile("cp.async.cg.shared.global [%0], [%1], 16;" :: "r"(saddr), "l"(g));
}
#define CP_COMMIT() asm volatile("cp.async.commit_group;" ::: "memory")
template<int N> __device__ __forceinline__ void cp_wait() {
    asm volatile("cp.async.wait_group %0;" :: "n"(N) : "memory");
}
__device__ __forceinline__ void split2(float v, bf16& h, bf16& l) {
    h = __float2bfloat16(v);
    l = __float2bfloat16(v - __bfloat162float(h));
}

// generic 128x128 warp-tiled split-bf16 MMA phase:
// 8 warps, warp tile 32x64; A/B planes in smem with halfword stride AS, NKS k16 steps.
template<int AS, int NKS>
__device__ __forceinline__ void mma_tile(uint32_t sb, uint32_t oAH, uint32_t oAL,
                                         uint32_t oBH, uint32_t oBL,
                                         float acc[2][8][4], int wid, int lid) {
    int wm = wid >> 1, wn = wid & 1;
    int arow = wm * 32, brow = wn * 64;
    int lr = lid & 15, lc8 = (lid >> 4) << 3;
    #pragma unroll
    for (int ks = 0; ks < NKS; ks++) {
        int k0 = ks * 16;
        uint32_t ah[2][4], al[2][4];
        #pragma unroll
        for (int mi = 0; mi < 2; mi++) {
            uint32_t off = (uint32_t)(((arow + mi * 16 + lr) * AS + k0 + lc8) * 2);
            ldsm_x4(sb + oAH + off, ah[mi][0], ah[mi][1], ah[mi][2], ah[mi][3]);
            ldsm_x4(sb + oAL + off, al[mi][0], al[mi][1], al[mi][2], al[mi][3]);
        }
        uint32_t bh[8][2], bl[8][2];
        #pragma unroll
        for (int nj = 0; nj < 4; nj++) {
            uint32_t off = (uint32_t)(((brow + nj * 16 + lr) * AS + k0 + lc8) * 2);
            uint32_t r0, r1, r2, r3;
            ldsm_x4(sb + oBH + off, r0, r1, r2, r3);
            bh[nj * 2][0] = r0; bh[nj * 2 + 1][0] = r1;
            bh[nj * 2][1] = r2; bh[nj * 2 + 1][1] = r3;
            ldsm_x4(sb + oBL + off, r0, r1, r2, r3);
            bl[nj * 2][0] = r0; bl[nj * 2 + 1][0] = r1;
            bl[nj * 2][1] = r2; bl[nj * 2 + 1][1] = r3;
        }
        #pragma unroll
        for (int mi = 0; mi < 2; mi++)
            #pragma unroll
            for (int n = 0; n < 8; n++) {
                mma_bf16(acc[mi][n], ah[mi], bh[n]);
                mma_bf16(acc[mi][n], ah[mi], bl[n]);
                mma_bf16(acc[mi][n], al[mi], bh[n]);
            }
    }
}

// ---------------- K0: fused prep (attn collapse + all weight splits) --------
__global__ void prep_all(const float* __restrict__ in_proj_w,
                         const float* __restrict__ in_proj_b,
                         const float* __restrict__ out_proj_w,
                         const float* __restrict__ out_proj_b,
                         const float* __restrict__ rec_emb,
                         const float* __restrict__ w1,
                         const float* __restrict__ w2) {
    int bid = blockIdx.x, tid = threadIdx.x;
    if (bid < 64) {                                   // M = Wo@Wv (+ c vector)
        int i = bid * 2 + (tid >> 7);
        int j = tid & 127;
        const float* Wv = in_proj_w + 2 * DIM * DIM;
        const float* bv = in_proj_b + 2 * DIM;
        float mv = 0.f;
        if (i < DIM && j < DIM) {
            #pragma unroll 4
            for (int k = 0; k < DIM; k++)
                mv += out_proj_w[i * DIM + k] * Wv[k * DIM + j];
        }
        split2(mv, g_Mh[i * KPAD + j], g_Ml[i * KPAD + j]);
        if (j == 0) {
            float s = 0.f;
            if (i < DIM) {
                s = out_proj_b[i];
                for (int k = 0; k < DIM; k++)
                    s += out_proj_w[i * DIM + k] * bv[k];
            }
            g_c[i] = s;
        }
    } else if (bid < 128) {                           // rec_emb split (64 blocks)
        int idx = (bid - 64) * 256 + tid;
        int n = idx >> 7, k = idx & 127;
        float v = (n < DIM && k < DIM) ? rec_emb[n * DIM + k] : 0.f;
        split2(v, g_rech[idx], g_recl[idx]);
    } else if (bid < 128 + 1024) {                    // W1 split
        int idx = (bid - 128) * 256 + tid;
        int n = idx >> 7, k = idx & 127;
        float v = (k < DIM) ? w1[n * DIM + k] : 0.f;
        split2(v, g_w1h[idx], g_w1l[idx]);
    } else {                                          // W2 split
        int idx = (bid - 1152) * 256 + tid;
        int n = idx >> 11, k = idx & 2047;
        float v = (n < DIM) ? w2[n * FFDIM + k] : 0.f;
        split2(v, g_w2h[idx], g_w2l[idx]);
    }
}

// ---------------- K1: embedding gather-sum ----------------------------------
__global__ void embed_sum(const int* __restrict__ seq,
                          const float* __restrict__ emb) {
    int b = blockIdx.x;
    __shared__ int s_idx[SEQ_L];
    int t = threadIdx.x;
    if (t < SEQ_L) s_idx[t] = seq[b * SEQ_L + t];
    __syncthreads();
    if (t < DIM) {
        float acc = 0.f;
        #pragma unroll 5
        for (int l = 0; l < SEQ_L; l++)
            acc += emb[(size_t)s_idx[l] * DIM + t];
        g_x[b * DIM + t] = acc;
    }
}

// ---------------- K2: fused attn + LN1 (tensor path, full-K tile) -----------
#define FAS 136
#define PL_SZ (128 * FAS * 2)
#define F_AH 0
#define F_AL PL_SZ
#define F_BH (2 * PL_SZ)
#define F_BL (3 * PL_SZ)
#define F_X  (4 * PL_SZ)
#define F_C  (4 * PL_SZ + 65536)
#define F_SMEM (F_C + 512)

__global__ __launch_bounds__(256, 1)
void attn_ln1_tc(const float* __restrict__ ln1_g, const float* __restrict__ ln1_b) {
    extern __shared__ char smem[];
    uint32_t sb = smem_u32(smem);
    int tid = threadIdx.x, wid = tid >> 5, lid = tid & 31;
    int m0 = blockIdx.x * 128;
    float* xbuf = (float*)(smem + F_X);
    float* cvec = (float*)(smem + F_C);
    if (tid < KPAD) cvec[tid] = g_c[tid];

    for (int idx = tid; idx < 128 * 128; idx += 256) {
        int r = idx >> 7, j = idx & 127;
        float v = (j < DIM) ? g_x[(size_t)(m0 + r) * DIM + j] : 0.f;
        xbuf[idx] = v;
        bf16 h, l; split2(v, h, l);
        *(bf16*)(smem + F_AH + ((r * FAS + j) << 1)) = h;
        *(bf16*)(smem + F_AL + ((r * FAS + j) << 1)) = l;
    }
    const uint4* BH4 = (const uint4*)g_Mh;
    const uint4* BL4 = (const uint4*)g_Ml;
    #pragma unroll
    for (int i = 0; i < 8; i++) {
        int idx = tid + i * 256;
        int r = idx >> 4, c = idx & 15;
        uint32_t so = (uint32_t)((r * FAS + c * 8) * 2);
        *(uint4*)(smem + F_BH + so) = BH4[r * 16 + c];
        *(uint4*)(smem + F_BL + so) = BL4[r * 16 + c];
    }
    __syncthreads();

    float acc[2][8][4] = {};
    mma_tile<FAS, 8>(sb, F_AH, F_AL, F_BH, F_BL, acc, wid, lid);
    __syncthreads();

    float* ybuf = (float*)(smem + F_AH);   // stride 132
    int wm = wid >> 1, wn = wid & 1;
    int arow = wm * 32, brow = wn * 64;
    #pragma unroll
    for (int mi = 0; mi < 2; mi++)
        #pragma unroll
        for (int n = 0; n < 8; n++) {
            int r = arow + mi * 16 + (lid >> 2);
            int c = brow + n * 8 + (lid & 3) * 2;
            ybuf[r * 132 + c]           = acc[mi][n][0] + xbuf[r * 128 + c]       + cvec[c];
            ybuf[r * 132 + c + 1]       = acc[mi][n][1] + xbuf[r * 128 + c + 1]   + cvec[c + 1];
            ybuf[(r + 8) * 132 + c]     = acc[mi][n][2] + xbuf[(r + 8) * 128 + c] + cvec[c];
            ybuf[(r + 8) * 132 + c + 1] = acc[mi][n][3] + xbuf[(r + 8) * 128 + c + 1] + cvec[c + 1];
        }
    __syncthreads();

    for (int rr = 0; rr < 16; rr++) {
        int r = wid * 16 + rr;
        float v[4], s = 0.f, sq = 0.f;
        #pragma unroll
        for (int q = 0; q < 4; q++) {
            int t = lid + q * 32;
            v[q] = (t < DIM) ? ybuf[r * 132 + t] : 0.f;
            s += v[q]; sq += v[q] * v[q];
        }
        #pragma unroll
        for (int off = 16; off; off >>= 1) {
            s  += __shfl_xor_sync(0xffffffffu, s,  off);
            sq += __shfl_xor_sync(0xffffffffu, sq, off);
        }
        float m = s / DIM;
        float inv = rsqrtf(sq / DIM - m * m + EPS);
        #pragma unroll
        for (int q = 0; q < 4; q++) {
            int t = lid + q * 32;
            float o = (t < DIM) ? (v[q] - m) * inv * ln1_g[t] + ln1_b[t] : 0.f;
            bf16 h, l; split2(o, h, l);
            g_x1h[(size_t)(m0 + r) * KPAD + t] = h;
            g_x1l[(size_t)(m0 + r) * KPAD + t] = l;
        }
    }
}

// ---------------- K3: GEMM1, K split into two 64-halves, occ=2 ---------------
#define AS1 72
#define P1SZ (128 * AS1 * 2)           // 18432
#define S1_AH 0
#define S1_AL P1SZ
#define S1_BH (2 * P1SZ)
#define S1_BL (3 * P1SZ)
#define S1_BIAS (4 * P1SZ)             // 73728
#define G1_SMEM (4 * P1SZ + 512)

__global__ __launch_bounds__(256, 2)
void gemm1_mma(const float* __restrict__ b1) {
    extern __shared__ char smem[];
    uint32_t sb = smem_u32(smem);
    int tid = threadIdx.x, wid = tid >> 5, lid = tid & 31;
    int m0 = blockIdx.x * 128, n0 = blockIdx.y * 128;
    float* bias = (float*)(smem + S1_BIAS);
    if (tid < 128) bias[tid] = b1[n0 + tid];

    const uint4* Ah = (const uint4*)g_x1h + (size_t)m0 * 16;
    const uint4* Al = (const uint4*)g_x1l + (size_t)m0 * 16;
    const uint4* Bh = (const uint4*)g_w1h + (size_t)n0 * 16;
    const uint4* Bl = (const uint4*)g_w1l + (size_t)n0 * 16;

    float acc[2][8][4] = {};
    #pragma unroll
    for (int kh = 0; kh < 2; kh++) {
        #pragma unroll
        for (int i = 0; i < 4; i++) {
            int idx = tid + i * 256;          // 0..1023
            int r = idx >> 3, c = idx & 7;
            uint32_t so = (uint32_t)((r * AS1 + c * 8) * 2);
            int gc = kh * 8 + c;
            *(uint4*)(smem + S1_AH + so) = Ah[r * 16 + gc];
            *(uint4*)(smem + S1_AL + so) = Al[r * 16 + gc];
            *(uint4*)(smem + S1_BH + so) = Bh[r * 16 + gc];
            *(uint4*)(smem + S1_BL + so) = Bl[r * 16 + gc];
        }
        __syncthreads();
        mma_tile<AS1, 4>(sb, S1_AH, S1_AL, S1_BH, S1_BL, acc, wid, lid);
        __syncthreads();
    }

    // epilogue: bias+relu+split staged in smem (stride 136), coalesced store
    int wm = wid >> 1, wn = wid & 1;
    int arow = wm * 32, brow = wn * 64;
    bf16* sh = (bf16*)(smem);
    bf16* sl = (bf16*)(smem + 34816);
    #pragma unroll
    for (int mi = 0; mi < 2; mi++)
        #pragma unroll
        for (int n = 0; n < 8; n++) {
            int r = arow + mi * 16 + (lid >> 2);
            int c = brow + n * 8 + (lid & 3) * 2;
            float v0 = fmaxf(acc[mi][n][0] + bias[c], 0.f);
            float v1 = fmaxf(acc[mi][n][1] + bias[c + 1], 0.f);
            float v2 = fmaxf(acc[mi][n][2] + bias[c], 0.f);
            float v3 = fmaxf(acc[mi][n][3] + bias[c + 1], 0.f);
            split2(v0, sh[r * 136 + c],           sl[r * 136 + c]);
            split2(v1, sh[r * 136 + c + 1],       sl[r * 136 + c + 1]);
            split2(v2, sh[(r + 8) * 136 + c],     sl[(r + 8) * 136 + c]);
            split2(v3, sh[(r + 8) * 136 + c + 1], sl[(r + 8) * 136 + c + 1]);
        }
    __syncthreads();
    uint4* HH = (uint4*)g_hh;
    uint4* HL = (uint4*)g_hl;
    #pragma unroll
    for (int i = 0; i < 8; i++) {
        int idx = tid + i * 256;
        int r = idx >> 4, c = idx & 15;
        uint32_t so = (uint32_t)((r * 136 + c * 8) * 2);
        HH[(size_t)(m0 + r) * 256 + (n0 >> 3) + c] = *(uint4*)(smem + so);
        HL[(size_t)(m0 + r) * 256 + (n0 >> 3) + c] = *(uint4*)(smem + 34816 + so);
    }
}

// ---------------- K4: GEMM2, K=32 chunks double-buffered, occ=2 --------------
#define AS2 40
#define ST_SZ (128 * AS2 * 2)          // 10240
#define BUF_SZ (4 * ST_SZ)             // 40960
#define S2_BIAS (2 * BUF_SZ)           // 81920
#define G2_SMEM (2 * BUF_SZ + 512)

__global__ __launch_bounds__(256, 2)
void gemm2_mma(const float* __restrict__ b2) {
    extern __shared__ char smem[];
    uint32_t sb = smem_u32(smem);
    int tid = threadIdx.x, wid = tid >> 5, lid = tid & 31;
    int m0 = blockIdx.x * 128;
    float* bias = (float*)(smem + S2_BIAS);
    if (tid < 128) bias[tid] = (tid < DIM) ? b2[tid] : 0.f;

    const uint4* srcAh = (const uint4*)g_hh + (size_t)m0 * 256;
    const uint4* srcAl = (const uint4*)g_hl + (size_t)m0 * 256;
    const uint4* srcBh = (const uint4*)g_w2h;
    const uint4* srcBl = (const uint4*)g_w2l;

    auto load_chunk = [&](int c, int buf) {
        uint32_t bb = sb + buf * BUF_SZ;
        #pragma unroll
        for (int i = 0; i < 2; i++) {
            int idx = tid + i * 256;       // 0..511
            int r = idx >> 2, cc = idx & 3;
            uint32_t so = (uint32_t)((r * AS2 + cc * 8) * 2);
            size_t go = (size_t)r * 256 + c * 4 + cc;
            cp16(bb + 0 * ST_SZ + so, srcAh + go);
            cp16(bb + 1 * ST_SZ + so, srcAl + go);
            cp16(bb + 2 * ST_SZ + so, srcBh + go);
            cp16(bb + 3 * ST_SZ + so, srcBl + go);
        }
    };

    float acc[2][8][4] = {};
    load_chunk(0, 0);
    CP_COMMIT();

    for (int c = 0; c < 64; c++) {
        if (c + 1 < 64) {
            load_chunk(c + 1, (c + 1) & 1);
            CP_COMMIT();
            cp_wait<1>();
        } else {
            cp_wait<0>();
        }
        __syncthreads();
        uint32_t bb = sb + (c & 1) * BUF_SZ;
        mma_tile<AS2, 2>(bb, 0, ST_SZ, 2 * ST_SZ, 3 * ST_SZ, acc, wid, lid);
        __syncthreads();
    }

    int wm = wid >> 1, wn = wid & 1;
    int arow = wm * 32, brow = wn * 64;
    #pragma unroll
    for (int mi = 0; mi < 2; mi++)
        #pragma unroll
        for (int n = 0; n < 8; n++) {
            int gr = m0 + arow + mi * 16 + (lid >> 2);
            int cc = brow + n * 8 + (lid & 3) * 2;
            if (cc < DIM) {
                g_ff[(size_t)gr * DIM + cc]       = acc[mi][n][0] + bias[cc];
                g_ff[(size_t)(gr + 8) * DIM + cc] = acc[mi][n][2] + bias[cc];
            }
            if (cc + 1 < DIM) {
                g_ff[(size_t)gr * DIM + cc + 1]       = acc[mi][n][1] + bias[cc + 1];
                g_ff[(size_t)(gr + 8) * DIM + cc + 1] = acc[mi][n][3] + bias[cc + 1];
            }
        }
}

// ---------------- K5: fused LN2 + scoring (tensor path) ----------------------
__global__ __launch_bounds__(256, 1)
void ln2_score_tc(const float* __restrict__ ln2_g, const float* __restrict__ ln2_b,
                  const int* __restrict__ items, const float* __restrict__ rec_b,
                  float* __restrict__ out) {
    extern __shared__ char smem[];
    uint32_t sb = smem_u32(smem);
    int tid = threadIdx.x, wid = tid >> 5, lid = tid & 31;
    int m0 = blockIdx.x * 128;
    float* fbuf = (float*)(smem + F_X);
    float* srecb = (float*)(smem + F_C);
    if (tid < KPAD) srecb[tid] = (tid < DIM) ? rec_b[tid] : 0.f;

    for (int idx = tid; idx < 128 * 128; idx += 256) {
        int r = idx >> 7, c = idx & 127;
        float v = 0.f;
        if (c < DIM)
            v = __bfloat162float(g_x1h[(size_t)(m0 + r) * KPAD + c])
              + __bfloat162float(g_x1l[(size_t)(m0 + r) * KPAD + c])
              + g_ff[(size_t)(m0 + r) * DIM + c];
        fbuf[idx] = v;
    }
    const uint4* BH4 = (const uint4*)g_rech;
    const uint4* BL4 = (const uint4*)g_recl;
    #pragma unroll
    for (int i = 0; i < 8; i++) {
        int idx = tid + i * 256;
        int r = idx >> 4, c = idx & 15;
        uint32_t so = (uint32_t)((r * FAS + c * 8) * 2);
        *(uint4*)(smem + F_BH + so) = BH4[r * 16 + c];
        *(uint4*)(smem + F_BL + so) = BL4[r * 16 + c];
    }
    __syncthreads();

    for (int rr = 0; rr < 16; rr++) {
        int r = wid * 16 + rr;
        float v[4], s = 0.f, sq = 0.f;
        #pragma unroll
        for (int q = 0; q < 4; q++) {
            int t = lid + q * 32;
            v[q] = (t < DIM) ? fbuf[r * 128 + t] : 0.f;
            s += v[q]; sq += v[q] * v[q];
        }
        #pragma unroll
        for (int off = 16; off; off >>= 1) {
            s  += __shfl_xor_sync(0xffffffffu, s,  off);
            sq += __shfl_xor_sync(0xffffffffu, sq, off);
        }
        float m = s / DIM;
        float inv = rsqrtf(sq / DIM - m * m + EPS);
        #pragma unroll
        for (int q = 0; q < 4; q++) {
            int t = lid + q * 32;
            float o = (t < DIM) ? (v[q] - m) * inv * ln2_g[t] + ln2_b[t] : 0.f;
            bf16 h, l; split2(o, h, l);
            *(bf16*)(smem + F_AH + ((r * FAS + t) << 1)) = h;
            *(bf16*)(smem + F_AL + ((r * FAS + t) << 1)) = l;
        }
    }
    __syncthreads();

    float acc[2][8][4] = {};
    mma_tile<FAS, 8>(sb, F_AH, F_AL, F_BH, F_BL, acc, wid, lid);
    __syncthreads();

    int wm = wid >> 1, wn = wid & 1;
    int arow = wm * 32, brow = wn * 64;
    #pragma unroll
    for (int mi = 0; mi < 2; mi++)
        #pragma unroll
        for (int n = 0; n < 8; n++) {
            int r = arow + mi * 16 + (lid >> 2);
            int c = brow + n * 8 + (lid & 3) * 2;
            fbuf[r * 128 + c]           = acc[mi][n][0];
            fbuf[r * 128 + c + 1]       = acc[mi][n][1];
            fbuf[(r + 8) * 128 + c]     = acc[mi][n][2];
            fbuf[(r + 8) * 128 + c + 1] = acc[mi][n][3];
        }
    __syncthreads();

    for (int o = tid; o < 128 * KPRED; o += 256) {
        int r = o / KPRED, k = o - r * KPRED;
        int idx = items[(size_t)(m0 + r) * KPRED + k];
        out[(size_t)(m0 + r) * KPRED + k] = fbuf[r * 128 + idx] + srecb[idx];
    }
}

// ---------------- launch ------------------------------------------------------
extern "C" void kernel_launch(void* const* d_in, const int* in_sizes, int n_in,
                              void* d_out, int out_size) {
    const int*   item_seq   = (const int*)  d_in[0];
    const int*   items_pred = (const int*)  d_in[1];
    const float* item_emb_w = (const float*)d_in[2];
    const float* rec_emb_w  = (const float*)d_in[3];
    const float* rec_b_w    = (const float*)d_in[4];
    const float* in_proj_w  = (const float*)d_in[5];
    const float* in_proj_b  = (const float*)d_in[6];
    const float* out_proj_w = (const float*)d_in[7];
    const float* out_proj_b = (const float*)d_in[8];
    const float* ln1_g      = (const float*)d_in[9];
    const float* ln1_b      = (const float*)d_in[10];
    const float* ln2_g      = (const float*)d_in[11];
    const float* ln2_b      = (const float*)d_in[12];
    const float* ffn_w1     = (const float*)d_in[13];
    const float* ffn_b1     = (const float*)d_in[14];
    const float* ffn_w2     = (const float*)d_in[15];
    const float* ffn_b2     = (const float*)d_in[16];
    float* out = (float*)d_out;

    int B = in_sizes[0] / SEQ_L;

    cudaFuncSetAttribute(attn_ln1_tc,  cudaFuncAttributeMaxDynamicSharedMemorySize, F_SMEM);
    cudaFuncSetAttribute(ln2_score_tc, cudaFuncAttributeMaxDynamicSharedMemorySize, F_SMEM);
    cudaFuncSetAttribute(gemm1_mma, cudaFuncAttributeMaxDynamicSharedMemorySize, G1_SMEM);
    cudaFuncSetAttribute(gemm2_mma, cudaFuncAttributeMaxDynamicSharedMemorySize, G2_SMEM);

    prep_all<<<2176, 256>>>(in_proj_w, in_proj_b, out_proj_w, out_proj_b,
                            rec_emb_w, ffn_w1, ffn_w2);
    embed_sum<<<B, 128>>>(item_seq, item_emb_w);
    attn_ln1_tc<<<B / 128, 256, F_SMEM>>>(ln1_g, ln1_b);
    gemm1_mma<<<dim3(B / 128, FFDIM / 128), 256, G1_SMEM>>>(ffn_b1);
    gemm2_mma<<<B / 128, 256, G2_SMEM>>>(ffn_b2);
    ln2_score_tc<<<B / 128, 256, F_SMEM>>>(ln2_g, ln2_b, items_pred, rec_b_w, out);
}

// round 6
// speedup vs baseline: 1.2268x; 1.2268x over previous
#include <cuda_runtime.h>
#include <cuda_fp16.h>
#include <cstdint>

#define SEQ_L 50
#define DIM 100
#define KPAD 128
#define FFDIM 2048
#define KPRED 100
#define EPS 1e-5f
#define BMAX 16384

typedef __half fp16;

// ---------------- scratch (device globals) ---------------------------------
__device__ float g_x  [BMAX * DIM];                   // embedding sums
__device__ float g_x1 [BMAX * KPAD];                  // LN1 out fp32 (residual path)
__device__ float g_ff [BMAX * DIM];
__device__ float g_c  [KPAD];
__device__ fp16  g_Mh [KPAD * KPAD],  g_Ml [KPAD * KPAD];   // attn matrix split
__device__ fp16  g_rech[KPAD * KPAD], g_recl[KPAD * KPAD];  // rec_emb split
__device__ fp16  g_x1f[BMAX * KPAD];                  // LN1 out fp16 (MMA operand)
__device__ fp16  g_w1h[FFDIM * KPAD], g_w1l[FFDIM * KPAD];
__device__ fp16  g_hf [(size_t)BMAX * FFDIM];         // hidden, single fp16 plane
__device__ fp16  g_w2h[KPAD * FFDIM], g_w2l[KPAD * FFDIM];

// ---------------- helpers ----------------------------------------------------
__device__ __forceinline__ uint32_t smem_u32(const void* p) {
    uint32_t a;
    asm("{ .reg .u64 t; cvta.to.shared.u64 t, %1; cvt.u32.u64 %0, t; }" : "=r"(a) : "l"(p));
    return a;
}
__device__ __forceinline__ void ldsm_x4(uint32_t addr, uint32_t& r0, uint32_t& r1,
                                        uint32_t& r2, uint32_t& r3) {
    asm volatile("ldmatrix.sync.aligned.m8n8.x4.shared.b16 {%0,%1,%2,%3}, [%4];"
                 : "=r"(r0), "=r"(r1), "=r"(r2), "=r"(r3) : "r"(addr));
}
__device__ __forceinline__ void mma_f16(float* d, const uint32_t* a, const uint32_t* b) {
    asm volatile("mma.sync.aligned.m16n8k16.row.col.f32.f16.f16.f32 "
                 "{%0,%1,%2,%3}, {%4,%5,%6,%7}, {%8,%9}, {%0,%1,%2,%3};"
                 : "+f"(d[0]), "+f"(d[1]), "+f"(d[2]), "+f"(d[3])
                 : "r"(a[0]), "r"(a[1]), "r"(a[2]), "r"(a[3]), "r"(b[0]), "r"(b[1]));
}
__device__ __forceinline__ void cp16(uint32_t saddr, const void* g) {
    asm volatile("cp.async.cg.shared.global [%0], [%1], 16;" :: "r"(saddr), "l"(g));
}
#define CP_COMMIT() asm volatile("cp.async.commit_group;" ::: "memory")
template<int N> __device__ __forceinline__ void cp_wait() {
    asm volatile("cp.async.wait_group %0;" :: "n"(N) : "memory");
}
__device__ __forceinline__ void split2h(float v, fp16& h, fp16& l) {
    h = __float2half_rn(v);
    l = __float2half_rn(v - __half2float(h));
}

// 128x128 warp-tiled MMA phase: A single fp16 plane, B split (hi/lo) planes.
// 8 warps, warp tile 32x64; halfword stride AS; NKS k16 steps. 2 MMAs per (mi,n).
template<int AS, int NKS>
__device__ __forceinline__ void mma_tile2(uint32_t sb, uint32_t oA, uint32_t oBH,
                                          uint32_t oBL, float acc[2][8][4],
                                          int wid, int lid) {
    int wm = wid >> 1, wn = wid & 1;
    int arow = wm * 32, brow = wn * 64;
    int lr = lid & 15, lc8 = (lid >> 4) << 3;
    #pragma unroll
    for (int ks = 0; ks < NKS; ks++) {
        int k0 = ks * 16;
        uint32_t a[2][4];
        #pragma unroll
        for (int mi = 0; mi < 2; mi++) {
            uint32_t off = (uint32_t)(((arow + mi * 16 + lr) * AS + k0 + lc8) * 2);
            ldsm_x4(sb + oA + off, a[mi][0], a[mi][1], a[mi][2], a[mi][3]);
        }
        uint32_t bh[8][2], bl[8][2];
        #pragma unroll
        for (int nj = 0; nj < 4; nj++) {
            uint32_t off = (uint32_t)(((brow + nj * 16 + lr) * AS + k0 + lc8) * 2);
            uint32_t r0, r1, r2, r3;
            ldsm_x4(sb + oBH + off, r0, r1, r2, r3);
            bh[nj * 2][0] = r0; bh[nj * 2 + 1][0] = r1;
            bh[nj * 2][1] = r2; bh[nj * 2 + 1][1] = r3;
            ldsm_x4(sb + oBL + off, r0, r1, r2, r3);
            bl[nj * 2][0] = r0; bl[nj * 2 + 1][0] = r1;
            bl[nj * 2][1] = r2; bl[nj * 2 + 1][1] = r3;
        }
        #pragma unroll
        for (int mi = 0; mi < 2; mi++)
            #pragma unroll
            for (int n = 0; n < 8; n++) {
                mma_f16(acc[mi][n], a[mi], bh[n]);
                mma_f16(acc[mi][n], a[mi], bl[n]);
            }
    }
}

// ---------------- K0: fused prep (attn collapse + all weight splits) --------
__global__ void prep_all(const float* __restrict__ in_proj_w,
                         const float* __restrict__ in_proj_b,
                         const float* __restrict__ out_proj_w,
                         const float* __restrict__ out_proj_b,
                         const float* __restrict__ rec_emb,
                         const float* __restrict__ w1,
                         const float* __restrict__ w2) {
    int bid = blockIdx.x, tid = threadIdx.x;
    if (bid < 64) {                                   // M = Wo@Wv (+ c vector)
        int i = bid * 2 + (tid >> 7);
        int j = tid & 127;
        const float* Wv = in_proj_w + 2 * DIM * DIM;
        const float* bv = in_proj_b + 2 * DIM;
        float mv = 0.f;
        if (i < DIM && j < DIM) {
            #pragma unroll 4
            for (int k = 0; k < DIM; k++)
                mv += out_proj_w[i * DIM + k] * Wv[k * DIM + j];
        }
        split2h(mv, g_Mh[i * KPAD + j], g_Ml[i * KPAD + j]);
        if (j == 0) {
            float s = 0.f;
            if (i < DIM) {
                s = out_proj_b[i];
                for (int k = 0; k < DIM; k++)
                    s += out_proj_w[i * DIM + k] * bv[k];
            }
            g_c[i] = s;
        }
    } else if (bid < 128) {                           // rec_emb split
        int idx = (bid - 64) * 256 + tid;
        int n = idx >> 7, k = idx & 127;
        float v = (n < DIM && k < DIM) ? rec_emb[n * DIM + k] : 0.f;
        split2h(v, g_rech[idx], g_recl[idx]);
    } else if (bid < 128 + 1024) {                    // W1 split
        int idx = (bid - 128) * 256 + tid;
        int n = idx >> 7, k = idx & 127;
        float v = (k < DIM) ? w1[n * DIM + k] : 0.f;
        split2h(v, g_w1h[idx], g_w1l[idx]);
    } else {                                          // W2 split
        int idx = (bid - 1152) * 256 + tid;
        int n = idx >> 11, k = idx & 2047;
        float v = (n < DIM) ? w2[n * FFDIM + k] : 0.f;
        split2h(v, g_w2h[idx], g_w2l[idx]);
    }
}

// ---------------- K1: embedding gather-sum ----------------------------------
__global__ void embed_sum(const int* __restrict__ seq,
                          const float* __restrict__ emb) {
    int b = blockIdx.x;
    __shared__ int s_idx[SEQ_L];
    int t = threadIdx.x;
    if (t < SEQ_L) s_idx[t] = seq[b * SEQ_L + t];
    __syncthreads();
    if (t < DIM) {
        float acc = 0.f;
        #pragma unroll 5
        for (int l = 0; l < SEQ_L; l++)
            acc += emb[(size_t)s_idx[l] * DIM + t];
        g_x[b * DIM + t] = acc;
    }
}

// ---------------- fused-tile smem layout (attn_ln1 / ln2_score) -------------
#define FAS 136
#define PL_SZ (128 * FAS * 2)          // 34816
#define F_A  0
#define F_BH PL_SZ
#define F_BL (2 * PL_SZ)
#define F_X  (3 * PL_SZ)               // fp32 128x128 buffer (65536)
#define F_C  (3 * PL_SZ + 65536)
#define F_SMEM (F_C + 512)

// ---------------- K2: fused attn + LN1 --------------------------------------
__global__ __launch_bounds__(256, 1)
void attn_ln1_tc(const float* __restrict__ ln1_g, const float* __restrict__ ln1_b) {
    extern __shared__ char smem[];
    uint32_t sb = smem_u32(smem);
    int tid = threadIdx.x, wid = tid >> 5, lid = tid & 31;
    int m0 = blockIdx.x * 128;
    float* xbuf = (float*)(smem + F_X);
    float* cvec = (float*)(smem + F_C);
    if (tid < KPAD) cvec[tid] = g_c[tid];

    for (int idx = tid; idx < 128 * 128; idx += 256) {
        int r = idx >> 7, j = idx & 127;
        float v = (j < DIM) ? g_x[(size_t)(m0 + r) * DIM + j] : 0.f;
        xbuf[idx] = v;
        *(fp16*)(smem + F_A + ((r * FAS + j) << 1)) = __float2half_rn(v);
    }
    const uint4* BH4 = (const uint4*)g_Mh;
    const uint4* BL4 = (const uint4*)g_Ml;
    #pragma unroll
    for (int i = 0; i < 8; i++) {
        int idx = tid + i * 256;
        int r = idx >> 4, c = idx & 15;
        uint32_t so = (uint32_t)((r * FAS + c * 8) * 2);
        *(uint4*)(smem + F_BH + so) = BH4[r * 16 + c];
        *(uint4*)(smem + F_BL + so) = BL4[r * 16 + c];
    }
    __syncthreads();

    float acc[2][8][4] = {};
    mma_tile2<FAS, 8>(sb, F_A, F_BH, F_BL, acc, wid, lid);
    __syncthreads();

    float* ybuf = (float*)(smem + F_A);    // stride 132 floats
    int wm = wid >> 1, wn = wid & 1;
    int arow = wm * 32, brow = wn * 64;
    #pragma unroll
    for (int mi = 0; mi < 2; mi++)
        #pragma unroll
        for (int n = 0; n < 8; n++) {
            int r = arow + mi * 16 + (lid >> 2);
            int c = brow + n * 8 + (lid & 3) * 2;
            ybuf[r * 132 + c]           = acc[mi][n][0] + xbuf[r * 128 + c]       + cvec[c];
            ybuf[r * 132 + c + 1]       = acc[mi][n][1] + xbuf[r * 128 + c + 1]   + cvec[c + 1];
            ybuf[(r + 8) * 132 + c]     = acc[mi][n][2] + xbuf[(r + 8) * 128 + c] + cvec[c];
            ybuf[(r + 8) * 132 + c + 1] = acc[mi][n][3] + xbuf[(r + 8) * 128 + c + 1] + cvec[c + 1];
        }
    __syncthreads();

    for (int rr = 0; rr < 16; rr++) {
        int r = wid * 16 + rr;
        float v[4], s = 0.f, sq = 0.f;
        #pragma unroll
        for (int q = 0; q < 4; q++) {
            int t = lid + q * 32;
            v[q] = (t < DIM) ? ybuf[r * 132 + t] : 0.f;
            s += v[q]; sq += v[q] * v[q];
        }
        #pragma unroll
        for (int off = 16; off; off >>= 1) {
            s  += __shfl_xor_sync(0xffffffffu, s,  off);
            sq += __shfl_xor_sync(0xffffffffu, sq, off);
        }
        float m = s / DIM;
        float inv = rsqrtf(sq / DIM - m * m + EPS);
        #pragma unroll
        for (int q = 0; q < 4; q++) {
            int t = lid + q * 32;
            float o = (t < DIM) ? (v[q] - m) * inv * ln1_g[t] + ln1_b[t] : 0.f;
            g_x1 [(size_t)(m0 + r) * KPAD + t] = o;
            g_x1f[(size_t)(m0 + r) * KPAD + t] = __float2half_rn(o);
        }
    }
}

// ---------------- K3: GEMM1: h = relu(x1 @ W1^T + b1), two K=64 phases -------
#define AS1 72
#define P1SZ (128 * AS1 * 2)           // 18432
#define S1_A  0
#define S1_BH P1SZ
#define S1_BL (2 * P1SZ)
#define S1_BIAS (3 * P1SZ)             // 55296
#define G1_SMEM (3 * P1SZ + 512)

__global__ __launch_bounds__(256, 2)
void gemm1_mma(const float* __restrict__ b1) {
    extern __shared__ char smem[];
    uint32_t sb = smem_u32(smem);
    int tid = threadIdx.x, wid = tid >> 5, lid = tid & 31;
    int m0 = blockIdx.x * 128, n0 = blockIdx.y * 128;
    float* bias = (float*)(smem + S1_BIAS);
    if (tid < 128) bias[tid] = b1[n0 + tid];

    const uint4* A4 = (const uint4*)g_x1f + (size_t)m0 * 16;
    const uint4* Bh = (const uint4*)g_w1h + (size_t)n0 * 16;
    const uint4* Bl = (const uint4*)g_w1l + (size_t)n0 * 16;

    float acc[2][8][4] = {};
    #pragma unroll
    for (int kh = 0; kh < 2; kh++) {
        #pragma unroll
        for (int i = 0; i < 4; i++) {
            int idx = tid + i * 256;          // 0..1023
            int r = idx >> 3, c = idx & 7;
            uint32_t so = (uint32_t)((r * AS1 + c * 8) * 2);
            int gc = kh * 8 + c;
            *(uint4*)(smem + S1_A  + so) = A4[r * 16 + gc];
            *(uint4*)(smem + S1_BH + so) = Bh[r * 16 + gc];
            *(uint4*)(smem + S1_BL + so) = Bl[r * 16 + gc];
        }
        __syncthreads();
        mma_tile2<AS1, 4>(sb, S1_A, S1_BH, S1_BL, acc, wid, lid);
        __syncthreads();
    }

    // epilogue: bias + relu -> single fp16 plane, staged for coalesced store
    int wm = wid >> 1, wn = wid & 1;
    int arow = wm * 32, brow = wn * 64;
    fp16* sh = (fp16*)smem;                 // stride 136 halves
    #pragma unroll
    for (int mi = 0; mi < 2; mi++)
        #pragma unroll
        for (int n = 0; n < 8; n++) {
            int r = arow + mi * 16 + (lid >> 2);
            int c = brow + n * 8 + (lid & 3) * 2;
            sh[r * 136 + c]           = __float2half_rn(fmaxf(acc[mi][n][0] + bias[c], 0.f));
            sh[r * 136 + c + 1]       = __float2half_rn(fmaxf(acc[mi][n][1] + bias[c + 1], 0.f));
            sh[(r + 8) * 136 + c]     = __float2half_rn(fmaxf(acc[mi][n][2] + bias[c], 0.f));
            sh[(r + 8) * 136 + c + 1] = __float2half_rn(fmaxf(acc[mi][n][3] + bias[c + 1], 0.f));
        }
    __syncthreads();
    uint4* HF = (uint4*)g_hf;
    #pragma unroll
    for (int i = 0; i < 8; i++) {
        int idx = tid + i * 256;
        int r = idx >> 4, c = idx & 15;
        uint32_t so = (uint32_t)((r * 136 + c * 8) * 2);
        HF[(size_t)(m0 + r) * 256 + (n0 >> 3) + c] = *(uint4*)(smem + so);
    }
}

// ---------------- K4: GEMM2: ff = h @ W2^T + b2, K=32 double-buffered --------
#define AS2 40
#define ST_SZ (128 * AS2 * 2)          // 10240 per plane
#define BUF_SZ (3 * ST_SZ)             // 30720 per stage
#define S2_BIAS (2 * BUF_SZ)           // 61440
#define G2_SMEM (2 * BUF_SZ + 512)

__global__ __launch_bounds__(256, 2)
void gemm2_mma(const float* __restrict__ b2) {
    extern __shared__ char smem[];
    uint32_t sb = smem_u32(smem);
    int tid = threadIdx.x, wid = tid >> 5, lid = tid & 31;
    int m0 = blockIdx.x * 128;
    float* bias = (float*)(smem + S2_BIAS);
    if (tid < 128) bias[tid] = (tid < DIM) ? b2[tid] : 0.f;

    const uint4* srcA  = (const uint4*)g_hf  + (size_t)m0 * 256;
    const uint4* srcBh = (const uint4*)g_w2h;
    const uint4* srcBl = (const uint4*)g_w2l;

    auto load_chunk = [&](int c, int buf) {
        uint32_t bb = sb + buf * BUF_SZ;
        #pragma unroll
        for (int i = 0; i < 2; i++) {
            int idx = tid + i * 256;       // 0..511
            int r = idx >> 2, cc = idx & 3;
            uint32_t so = (uint32_t)((r * AS2 + cc * 8) * 2);
            size_t go = (size_t)r * 256 + c * 4 + cc;
            cp16(bb + 0 * ST_SZ + so, srcA  + go);
            cp16(bb + 1 * ST_SZ + so, srcBh + go);
            cp16(bb + 2 * ST_SZ + so, srcBl + go);
        }
    };

    float acc[2][8][4] = {};
    load_chunk(0, 0);
    CP_COMMIT();

    for (int c = 0; c < 64; c++) {
        if (c + 1 < 64) {
            load_chunk(c + 1, (c + 1) & 1);
            CP_COMMIT();
            cp_wait<1>();
        } else {
            cp_wait<0>();
        }
        __syncthreads();
        uint32_t bb = sb + (c & 1) * BUF_SZ;
        mma_tile2<AS2, 2>(bb, 0, ST_SZ, 2 * ST_SZ, acc, wid, lid);
        __syncthreads();
    }

    int wm = wid >> 1, wn = wid & 1;
    int arow = wm * 32, brow = wn * 64;
    #pragma unroll
    for (int mi = 0; mi < 2; mi++)
        #pragma unroll
        for (int n = 0; n < 8; n++) {
            int gr = m0 + arow + mi * 16 + (lid >> 2);
            int cc = brow + n * 8 + (lid & 3) * 2;
            if (cc < DIM) {
                g_ff[(size_t)gr * DIM + cc]       = acc[mi][n][0] + bias[cc];
                g_ff[(size_t)(gr + 8) * DIM + cc] = acc[mi][n][2] + bias[cc];
            }
            if (cc + 1 < DIM) {
                g_ff[(size_t)gr * DIM + cc + 1]       = acc[mi][n][1] + bias[cc + 1];
                g_ff[(size_t)(gr + 8) * DIM + cc + 1] = acc[mi][n][3] + bias[cc + 1];
            }
        }
}

// ---------------- K5: fused LN2 + scoring ------------------------------------
__global__ __launch_bounds__(256, 1)
void ln2_score_tc(const float* __restrict__ ln2_g, const float* __restrict__ ln2_b,
                  const int* __restrict__ items, const float* __restrict__ rec_b,
                  float* __restrict__ out) {
    extern __shared__ char smem[];
    uint32_t sb = smem_u32(smem);
    int tid = threadIdx.x, wid = tid >> 5, lid = tid & 31;
    int m0 = blockIdx.x * 128;
    float* fbuf = (float*)(smem + F_X);
    float* srecb = (float*)(smem + F_C);
    if (tid < KPAD) srecb[tid] = (tid < DIM) ? rec_b[tid] : 0.f;

    // y = x1 (fp32 residual) + ff
    for (int idx = tid; idx < 128 * 128; idx += 256) {
        int r = idx >> 7, c = idx & 127;
        float v = 0.f;
        if (c < DIM)
            v = g_x1[(size_t)(m0 + r) * KPAD + c] + g_ff[(size_t)(m0 + r) * DIM + c];
        fbuf[idx] = v;
    }
    const uint4* BH4 = (const uint4*)g_rech;
    const uint4* BL4 = (const uint4*)g_recl;
    #pragma unroll
    for (int i = 0; i < 8; i++) {
        int idx = tid + i * 256;
        int r = idx >> 4, c = idx & 15;
        uint32_t so = (uint32_t)((r * FAS + c * 8) * 2);
        *(uint4*)(smem + F_BH + so) = BH4[r * 16 + c];
        *(uint4*)(smem + F_BL + so) = BL4[r * 16 + c];
    }
    __syncthreads();

    // LN per row -> single fp16 A plane
    for (int rr = 0; rr < 16; rr++) {
        int r = wid * 16 + rr;
        float v[4], s = 0.f, sq = 0.f;
        #pragma unroll
        for (int q = 0; q < 4; q++) {
            int t = lid + q * 32;
            v[q] = (t < DIM) ? fbuf[r * 128 + t] : 0.f;
            s += v[q]; sq += v[q] * v[q];
        }
        #pragma unroll
        for (int off = 16; off; off >>= 1) {
            s  += __shfl_xor_sync(0xffffffffu, s,  off);
            sq += __shfl_xor_sync(0xffffffffu, sq, off);
        }
        float m = s / DIM;
        float inv = rsqrtf(sq / DIM - m * m + EPS);
        #pragma unroll
        for (int q = 0; q < 4; q++) {
            int t = lid + q * 32;
            float o = (t < DIM) ? (v[q] - m) * inv * ln2_g[t] + ln2_b[t] : 0.f;
            *(fp16*)(smem + F_A + ((r * FAS + t) << 1)) = __float2half_rn(o);
        }
    }
    __syncthreads();

    float acc[2][8][4] = {};
    mma_tile2<FAS, 8>(sb, F_A, F_BH, F_BL, acc, wid, lid);
    __syncthreads();

    int wm = wid >> 1, wn = wid & 1;
    int arow = wm * 32, brow = wn * 64;
    #pragma unroll
    for (int mi = 0; mi < 2; mi++)
        #pragma unroll
        for (int n = 0; n < 8; n++) {
            int r = arow + mi * 16 + (lid >> 2);
            int c = brow + n * 8 + (lid & 3) * 2;
            fbuf[r * 128 + c]           = acc[mi][n][0];
            fbuf[r * 128 + c + 1]       = acc[mi][n][1];
            fbuf[(r + 8) * 128 + c]     = acc[mi][n][2];
            fbuf[(r + 8) * 128 + c + 1] = acc[mi][n][3];
        }
    __syncthreads();

    for (int o = tid; o < 128 * KPRED; o += 256) {
        int r = o / KPRED, k = o - r * KPRED;
        int idx = items[(size_t)(m0 + r) * KPRED + k];
        out[(size_t)(m0 + r) * KPRED + k] = fbuf[r * 128 + idx] + srecb[idx];
    }
}

// ---------------- launch ------------------------------------------------------
extern "C" void kernel_launch(void* const* d_in, const int* in_sizes, int n_in,
                              void* d_out, int out_size) {
    const int*   item_seq   = (const int*)  d_in[0];
    const int*   items_pred = (const int*)  d_in[1];
    const float* item_emb_w = (const float*)d_in[2];
    const float* rec_emb_w  = (const float*)d_in[3];
    const float* rec_b_w    = (const float*)d_in[4];
    const float* in_proj_w  = (const float*)d_in[5];
    const float* in_proj_b  = (const float*)d_in[6];
    const float* out_proj_w = (const float*)d_in[7];
    const float* out_proj_b = (const float*)d_in[8];
    const float* ln1_g      = (const float*)d_in[9];
    const float* ln1_b      = (const float*)d_in[10];
    const float* ln2_g      = (const float*)d_in[11];
    const float* ln2_b      = (const float*)d_in[12];
    const float* ffn_w1     = (const float*)d_in[13];
    const float* ffn_b1     = (const float*)d_in[14];
    const float* ffn_w2     = (const float*)d_in[15];
    const float* ffn_b2     = (const float*)d_in[16];
    float* out = (float*)d_out;

    int B = in_sizes[0] / SEQ_L;

    cudaFuncSetAttribute(attn_ln1_tc,  cudaFuncAttributeMaxDynamicSharedMemorySize, F_SMEM);
    cudaFuncSetAttribute(ln2_score_tc, cudaFuncAttributeMaxDynamicSharedMemorySize, F_SMEM);
    cudaFuncSetAttribute(gemm1_mma, cudaFuncAttributeMaxDynamicSharedMemorySize, G1_SMEM);
    cudaFuncSetAttribute(gemm2_mma, cudaFuncAttributeMaxDynamicSharedMemorySize, G2_SMEM);

    prep_all<<<2176, 256>>>(in_proj_w, in_proj_b, out_proj_w, out_proj_b,
                            rec_emb_w, ffn_w1, ffn_w2);
    embed_sum<<<B, 128>>>(item_seq, item_emb_w);
    attn_ln1_tc<<<B / 128, 256, F_SMEM>>>(ln1_g, ln1_b);
    gemm1_mma<<<dim3(B / 128, FFDIM / 128), 256, G1_SMEM>>>(ffn_b1);
    gemm2_mma<<<B / 128, 256, G2_SMEM>>>(ffn_b2);
    ln2_score_tc<<<B / 128, 256, F_SMEM>>>(ln2_g, ln2_b, items_pred, rec_b_w, out);
}

// round 7
// speedup vs baseline: 1.4453x; 1.1781x over previous
#include <cuda_runtime.h>
#include <cuda_fp16.h>
#include <cstdint>

#define SEQ_L 50
#define DIM 100
#define KPAD 128
#define FFDIM 2048
#define KPRED 100
#define EPS 1e-5f
#define BMAX 16384

typedef __half fp16;

// ---------------- scratch (device globals) ---------------------------------
__device__ float g_x  [BMAX * DIM];                   // embedding sums
__device__ float g_x1 [BMAX * KPAD];                  // LN1 out fp32 (residual)
__device__ float g_ff [BMAX * DIM];
__device__ float g_c  [KPAD];
__device__ fp16  g_Mf  [KPAD * KPAD];                 // attn matrix fp16
__device__ fp16  g_recf[KPAD * KPAD];                 // rec_emb fp16
__device__ fp16  g_x1f[BMAX * KPAD];                  // LN1 out fp16 (MMA operand)
__device__ fp16  g_w1f[FFDIM * KPAD];
__device__ fp16  g_hf [(size_t)BMAX * FFDIM];         // hidden fp16
__device__ fp16  g_w2f[KPAD * FFDIM];

// ---------------- helpers ----------------------------------------------------
__device__ __forceinline__ uint32_t smem_u32(const void* p) {
    uint32_t a;
    asm("{ .reg .u64 t; cvta.to.shared.u64 t, %1; cvt.u32.u64 %0, t; }" : "=r"(a) : "l"(p));
    return a;
}
__device__ __forceinline__ void ldsm_x4(uint32_t addr, uint32_t& r0, uint32_t& r1,
                                        uint32_t& r2, uint32_t& r3) {
    asm volatile("ldmatrix.sync.aligned.m8n8.x4.shared.b16 {%0,%1,%2,%3}, [%4];"
                 : "=r"(r0), "=r"(r1), "=r"(r2), "=r"(r3) : "r"(addr));
}
__device__ __forceinline__ void mma_f16(float* d, const uint32_t* a, const uint32_t* b) {
    asm volatile("mma.sync.aligned.m16n8k16.row.col.f32.f16.f16.f32 "
                 "{%0,%1,%2,%3}, {%4,%5,%6,%7}, {%8,%9}, {%0,%1,%2,%3};"
                 : "+f"(d[0]), "+f"(d[1]), "+f"(d[2]), "+f"(d[3])
                 : "r"(a[0]), "r"(a[1]), "r"(a[2]), "r"(a[3]), "r"(b[0]), "r"(b[1]));
}
__device__ __forceinline__ void cp16(uint32_t saddr, const void* g) {
    asm volatile("cp.async.cg.shared.global [%0], [%1], 16;" :: "r"(saddr), "l"(g));
}
#define CP_COMMIT() asm volatile("cp.async.commit_group;" ::: "memory")
template<int N> __device__ __forceinline__ void cp_wait() {
    asm volatile("cp.async.wait_group %0;" :: "n"(N) : "memory");
}

// 128x128 warp-tiled MMA phase: single fp16 A and B planes.
// 8 warps, warp tile 32x64; halfword stride AS; NKS k16 steps. 1 MMA per (mi,n).
template<int AS, int NKS>
__device__ __forceinline__ void mma_tile1(uint32_t sb, uint32_t oA, uint32_t oB,
                                          float acc[2][8][4], int wid, int lid) {
    int wm = wid >> 1, wn = wid & 1;
    int arow = wm * 32, brow = wn * 64;
    int lr = lid & 15, lc8 = (lid >> 4) << 3;
    #pragma unroll
    for (int ks = 0; ks < NKS; ks++) {
        int k0 = ks * 16;
        uint32_t a[2][4];
        #pragma unroll
        for (int mi = 0; mi < 2; mi++) {
            uint32_t off = (uint32_t)(((arow + mi * 16 + lr) * AS + k0 + lc8) * 2);
            ldsm_x4(sb + oA + off, a[mi][0], a[mi][1], a[mi][2], a[mi][3]);
        }
        uint32_t b[8][2];
        #pragma unroll
        for (int nj = 0; nj < 4; nj++) {
            uint32_t off = (uint32_t)(((brow + nj * 16 + lr) * AS + k0 + lc8) * 2);
            uint32_t r0, r1, r2, r3;
            ldsm_x4(sb + oB + off, r0, r1, r2, r3);
            b[nj * 2][0] = r0; b[nj * 2 + 1][0] = r1;
            b[nj * 2][1] = r2; b[nj * 2 + 1][1] = r3;
        }
        #pragma unroll
        for (int mi = 0; mi < 2; mi++)
            #pragma unroll
            for (int n = 0; n < 8; n++)
                mma_f16(acc[mi][n], a[mi], b[n]);
    }
}

// ---------------- K0: fused prep (attn collapse + weight conversions) --------
__global__ void prep_all(const float* __restrict__ in_proj_w,
                         const float* __restrict__ in_proj_b,
                         const float* __restrict__ out_proj_w,
                         const float* __restrict__ out_proj_b,
                         const float* __restrict__ rec_emb,
                         const float* __restrict__ w1,
                         const float* __restrict__ w2) {
    int bid = blockIdx.x, tid = threadIdx.x;
    if (bid < 64) {                                   // M = Wo@Wv (+ c vector)
        int i = bid * 2 + (tid >> 7);
        int j = tid & 127;
        const float* Wv = in_proj_w + 2 * DIM * DIM;
        const float* bv = in_proj_b + 2 * DIM;
        float mv = 0.f;
        if (i < DIM && j < DIM) {
            #pragma unroll 4
            for (int k = 0; k < DIM; k++)
                mv += out_proj_w[i * DIM + k] * Wv[k * DIM + j];
        }
        g_Mf[i * KPAD + j] = __float2half_rn(mv);
        if (j == 0) {
            float s = 0.f;
            if (i < DIM) {
                s = out_proj_b[i];
                for (int k = 0; k < DIM; k++)
                    s += out_proj_w[i * DIM + k] * bv[k];
            }
            g_c[i] = s;
        }
    } else if (bid < 128) {                           // rec_emb convert
        int idx = (bid - 64) * 256 + tid;
        int n = idx >> 7, k = idx & 127;
        float v = (n < DIM && k < DIM) ? rec_emb[n * DIM + k] : 0.f;
        g_recf[idx] = __float2half_rn(v);
    } else if (bid < 128 + 1024) {                    // W1 convert
        int idx = (bid - 128) * 256 + tid;
        int n = idx >> 7, k = idx & 127;
        float v = (k < DIM) ? w1[n * DIM + k] : 0.f;
        g_w1f[idx] = __float2half_rn(v);
    } else {                                          // W2 convert
        int idx = (bid - 1152) * 256 + tid;
        int n = idx >> 11, k = idx & 2047;
        float v = (n < DIM) ? w2[n * FFDIM + k] : 0.f;
        g_w2f[idx] = __float2half_rn(v);
    }
}

// ---------------- K1: embedding gather-sum ----------------------------------
__global__ void embed_sum(const int* __restrict__ seq,
                          const float* __restrict__ emb) {
    int b = blockIdx.x;
    __shared__ int s_idx[SEQ_L];
    int t = threadIdx.x;
    if (t < SEQ_L) s_idx[t] = seq[b * SEQ_L + t];
    __syncthreads();
    if (t < DIM) {
        float acc = 0.f;
        #pragma unroll 5
        for (int l = 0; l < SEQ_L; l++)
            acc += emb[(size_t)s_idx[l] * DIM + t];
        g_x[b * DIM + t] = acc;
    }
}

// ---------------- fused-tile smem layout (attn_ln1 / ln2_score) -------------
#define FAS 136
#define PL_SZ (128 * FAS * 2)          // 34816
#define F_A  0
#define F_B  PL_SZ
#define F_X  (2 * PL_SZ)               // fp32 128x128 buffer (65536)
#define F_C  (2 * PL_SZ + 65536)
#define F_SMEM (F_C + 512)

// ---------------- K2: fused attn + LN1 --------------------------------------
__global__ __launch_bounds__(256, 1)
void attn_ln1_tc(const float* __restrict__ ln1_g, const float* __restrict__ ln1_b) {
    extern __shared__ char smem[];
    uint32_t sb = smem_u32(smem);
    int tid = threadIdx.x, wid = tid >> 5, lid = tid & 31;
    int m0 = blockIdx.x * 128;
    float* xbuf = (float*)(smem + F_X);
    float* cvec = (float*)(smem + F_C);
    if (tid < KPAD) cvec[tid] = g_c[tid];

    for (int idx = tid; idx < 128 * 128; idx += 256) {
        int r = idx >> 7, j = idx & 127;
        float v = (j < DIM) ? g_x[(size_t)(m0 + r) * DIM + j] : 0.f;
        xbuf[idx] = v;
        *(fp16*)(smem + F_A + ((r * FAS + j) << 1)) = __float2half_rn(v);
    }
    const uint4* B4 = (const uint4*)g_Mf;
    #pragma unroll
    for (int i = 0; i < 8; i++) {
        int idx = tid + i * 256;
        int r = idx >> 4, c = idx & 15;
        uint32_t so = (uint32_t)((r * FAS + c * 8) * 2);
        *(uint4*)(smem + F_B + so) = B4[r * 16 + c];
    }
    __syncthreads();

    float acc[2][8][4] = {};
    mma_tile1<FAS, 8>(sb, F_A, F_B, acc, wid, lid);
    __syncthreads();

    float* ybuf = (float*)(smem + F_A);    // stride 132 floats
    int wm = wid >> 1, wn = wid & 1;
    int arow = wm * 32, brow = wn * 64;
    #pragma unroll
    for (int mi = 0; mi < 2; mi++)
        #pragma unroll
        for (int n = 0; n < 8; n++) {
            int r = arow + mi * 16 + (lid >> 2);
            int c = brow + n * 8 + (lid & 3) * 2;
            ybuf[r * 132 + c]           = acc[mi][n][0] + xbuf[r * 128 + c]       + cvec[c];
            ybuf[r * 132 + c + 1]       = acc[mi][n][1] + xbuf[r * 128 + c + 1]   + cvec[c + 1];
            ybuf[(r + 8) * 132 + c]     = acc[mi][n][2] + xbuf[(r + 8) * 128 + c] + cvec[c];
            ybuf[(r + 8) * 132 + c + 1] = acc[mi][n][3] + xbuf[(r + 8) * 128 + c + 1] + cvec[c + 1];
        }
    __syncthreads();

    for (int rr = 0; rr < 16; rr++) {
        int r = wid * 16 + rr;
        float v[4], s = 0.f, sq = 0.f;
        #pragma unroll
        for (int q = 0; q < 4; q++) {
            int t = lid + q * 32;
            v[q] = (t < DIM) ? ybuf[r * 132 + t] : 0.f;
            s += v[q]; sq += v[q] * v[q];
        }
        #pragma unroll
        for (int off = 16; off; off >>= 1) {
            s  += __shfl_xor_sync(0xffffffffu, s,  off);
            sq += __shfl_xor_sync(0xffffffffu, sq, off);
        }
        float m = s / DIM;
        float inv = rsqrtf(sq / DIM - m * m + EPS);
        #pragma unroll
        for (int q = 0; q < 4; q++) {
            int t = lid + q * 32;
            float o = (t < DIM) ? (v[q] - m) * inv * ln1_g[t] + ln1_b[t] : 0.f;
            g_x1 [(size_t)(m0 + r) * KPAD + t] = o;
            g_x1f[(size_t)(m0 + r) * KPAD + t] = __float2half_rn(o);
        }
    }
}

// ---------------- K3: GEMM1: h = relu(x1 @ W1^T + b1), two K=64 phases -------
#define AS1 72
#define P1SZ (128 * AS1 * 2)           // 18432
#define S1_A  0
#define S1_B  P1SZ
#define S1_BIAS (2 * P1SZ)             // 36864
#define G1_SMEM (2 * P1SZ + 512)

__global__ __launch_bounds__(256, 2)
void gemm1_mma(const float* __restrict__ b1) {
    extern __shared__ char smem[];
    uint32_t sb = smem_u32(smem);
    int tid = threadIdx.x, wid = tid >> 5, lid = tid & 31;
    int m0 = blockIdx.x * 128, n0 = blockIdx.y * 128;
    float* bias = (float*)(smem + S1_BIAS);
    if (tid < 128) bias[tid] = b1[n0 + tid];

    const uint4* A4 = (const uint4*)g_x1f + (size_t)m0 * 16;
    const uint4* B4 = (const uint4*)g_w1f + (size_t)n0 * 16;

    float acc[2][8][4] = {};
    #pragma unroll
    for (int kh = 0; kh < 2; kh++) {
        #pragma unroll
        for (int i = 0; i < 4; i++) {
            int idx = tid + i * 256;          // 0..1023
            int r = idx >> 3, c = idx & 7;
            uint32_t so = (uint32_t)((r * AS1 + c * 8) * 2);
            int gc = kh * 8 + c;
            *(uint4*)(smem + S1_A + so) = A4[r * 16 + gc];
            *(uint4*)(smem + S1_B + so) = B4[r * 16 + gc];
        }
        __syncthreads();
        mma_tile1<AS1, 4>(sb, S1_A, S1_B, acc, wid, lid);
        __syncthreads();
    }

    // epilogue: bias + relu -> fp16 plane, staged for coalesced store
    int wm = wid >> 1, wn = wid & 1;
    int arow = wm * 32, brow = wn * 64;
    fp16* sh = (fp16*)smem;                 // stride 136 halves
    #pragma unroll
    for (int mi = 0; mi < 2; mi++)
        #pragma unroll
        for (int n = 0; n < 8; n++) {
            int r = arow + mi * 16 + (lid >> 2);
            int c = brow + n * 8 + (lid & 3) * 2;
            sh[r * 136 + c]           = __float2half_rn(fmaxf(acc[mi][n][0] + bias[c], 0.f));
            sh[r * 136 + c + 1]       = __float2half_rn(fmaxf(acc[mi][n][1] + bias[c + 1], 0.f));
            sh[(r + 8) * 136 + c]     = __float2half_rn(fmaxf(acc[mi][n][2] + bias[c], 0.f));
            sh[(r + 8) * 136 + c + 1] = __float2half_rn(fmaxf(acc[mi][n][3] + bias[c + 1], 0.f));
        }
    __syncthreads();
    uint4* HF = (uint4*)g_hf;
    #pragma unroll
    for (int i = 0; i < 8; i++) {
        int idx = tid + i * 256;
        int r = idx >> 4, c = idx & 15;
        uint32_t so = (uint32_t)((r * 136 + c * 8) * 2);
        HF[(size_t)(m0 + r) * 256 + (n0 >> 3) + c] = *(uint4*)(smem + so);
    }
}

// ---------------- K4: GEMM2: ff = h @ W2^T + b2, K=32 double-buffered --------
#define AS2 40
#define ST_SZ (128 * AS2 * 2)          // 10240 per plane
#define BUF_SZ (2 * ST_SZ)             // 20480 per stage
#define S2_BIAS (2 * BUF_SZ)           // 40960
#define G2_SMEM (2 * BUF_SZ + 512)

__global__ __launch_bounds__(256, 2)
void gemm2_mma(const float* __restrict__ b2) {
    extern __shared__ char smem[];
    uint32_t sb = smem_u32(smem);
    int tid = threadIdx.x, wid = tid >> 5, lid = tid & 31;
    int m0 = blockIdx.x * 128;
    float* bias = (float*)(smem + S2_BIAS);
    if (tid < 128) bias[tid] = (tid < DIM) ? b2[tid] : 0.f;

    const uint4* srcA = (const uint4*)g_hf  + (size_t)m0 * 256;
    const uint4* srcB = (const uint4*)g_w2f;

    auto load_chunk = [&](int c, int buf) {
        uint32_t bb = sb + buf * BUF_SZ;
        #pragma unroll
        for (int i = 0; i < 2; i++) {
            int idx = tid + i * 256;       // 0..511
            int r = idx >> 2, cc = idx & 3;
            uint32_t so = (uint32_t)((r * AS2 + cc * 8) * 2);
            size_t go = (size_t)r * 256 + c * 4 + cc;
            cp16(bb + 0 * ST_SZ + so, srcA + go);
            cp16(bb + 1 * ST_SZ + so, srcB + go);
        }
    };

    float acc[2][8][4] = {};
    load_chunk(0, 0);
    CP_COMMIT();

    for (int c = 0; c < 64; c++) {
        if (c + 1 < 64) {
            load_chunk(c + 1, (c + 1) & 1);
            CP_COMMIT();
            cp_wait<1>();
        } else {
            cp_wait<0>();
        }
        __syncthreads();
        uint32_t bb = sb + (c & 1) * BUF_SZ;
        mma_tile1<AS2, 2>(bb, 0, ST_SZ, acc, wid, lid);
        __syncthreads();
    }

    int wm = wid >> 1, wn = wid & 1;
    int arow = wm * 32, brow = wn * 64;
    #pragma unroll
    for (int mi = 0; mi < 2; mi++)
        #pragma unroll
        for (int n = 0; n < 8; n++) {
            int gr = m0 + arow + mi * 16 + (lid >> 2);
            int cc = brow + n * 8 + (lid & 3) * 2;
            if (cc < DIM) {
                g_ff[(size_t)gr * DIM + cc]       = acc[mi][n][0] + bias[cc];
                g_ff[(size_t)(gr + 8) * DIM + cc] = acc[mi][n][2] + bias[cc];
            }
            if (cc + 1 < DIM) {
                g_ff[(size_t)gr * DIM + cc + 1]       = acc[mi][n][1] + bias[cc + 1];
                g_ff[(size_t)(gr + 8) * DIM + cc + 1] = acc[mi][n][3] + bias[cc + 1];
            }
        }
}

// ---------------- K5: fused LN2 + scoring ------------------------------------
__global__ __launch_bounds__(256, 1)
void ln2_score_tc(const float* __restrict__ ln2_g, const float* __restrict__ ln2_b,
                  const int* __restrict__ items, const float* __restrict__ rec_b,
                  float* __restrict__ out) {
    extern __shared__ char smem[];
    uint32_t sb = smem_u32(smem);
    int tid = threadIdx.x, wid = tid >> 5, lid = tid & 31;
    int m0 = blockIdx.x * 128;
    float* fbuf = (float*)(smem + F_X);
    float* srecb = (float*)(smem + F_C);
    if (tid < KPAD) srecb[tid] = (tid < DIM) ? rec_b[tid] : 0.f;

    for (int idx = tid; idx < 128 * 128; idx += 256) {
        int r = idx >> 7, c = idx & 127;
        float v = 0.f;
        if (c < DIM)
            v = g_x1[(size_t)(m0 + r) * KPAD + c] + g_ff[(size_t)(m0 + r) * DIM + c];
        fbuf[idx] = v;
    }
    const uint4* B4 = (const uint4*)g_recf;
    #pragma unroll
    for (int i = 0; i < 8; i++) {
        int idx = tid + i * 256;
        int r = idx >> 4, c = idx & 15;
        uint32_t so = (uint32_t)((r * FAS + c * 8) * 2);
        *(uint4*)(smem + F_B + so) = B4[r * 16 + c];
    }
    __syncthreads();

    for (int rr = 0; rr < 16; rr++) {
        int r = wid * 16 + rr;
        float v[4], s = 0.f, sq = 0.f;
        #pragma unroll
        for (int q = 0; q < 4; q++) {
            int t = lid + q * 32;
            v[q] = (t < DIM) ? fbuf[r * 128 + t] : 0.f;
            s += v[q]; sq += v[q] * v[q];
        }
        #pragma unroll
        for (int off = 16; off; off >>= 1) {
            s  += __shfl_xor_sync(0xffffffffu, s,  off);
            sq += __shfl_xor_sync(0xffffffffu, sq, off);
        }
        float m = s / DIM;
        float inv = rsqrtf(sq / DIM - m * m + EPS);
        #pragma unroll
        for (int q = 0; q < 4; q++) {
            int t = lid + q * 32;
            float o = (t < DIM) ? (v[q] - m) * inv * ln2_g[t] + ln2_b[t] : 0.f;
            *(fp16*)(smem + F_A + ((r * FAS + t) << 1)) = __float2half_rn(o);
        }
    }
    __syncthreads();

    float acc[2][8][4] = {};
    mma_tile1<FAS, 8>(sb, F_A, F_B, acc, wid, lid);
    __syncthreads();

    int wm = wid >> 1, wn = wid & 1;
    int arow = wm * 32, brow = wn * 64;
    #pragma unroll
    for (int mi = 0; mi < 2; mi++)
        #pragma unroll
        for (int n = 0; n < 8; n++) {
            int r = arow + mi * 16 + (lid >> 2);
            int c = brow + n * 8 + (lid & 3) * 2;
            fbuf[r * 128 + c]           = acc[mi][n][0];
            fbuf[r * 128 + c + 1]       = acc[mi][n][1];
            fbuf[(r + 8) * 128 + c]     = acc[mi][n][2];
            fbuf[(r + 8) * 128 + c + 1] = acc[mi][n][3];
        }
    __syncthreads();

    for (int o = tid; o < 128 * KPRED; o += 256) {
        int r = o / KPRED, k = o - r * KPRED;
        int idx = items[(size_t)(m0 + r) * KPRED + k];
        out[(size_t)(m0 + r) * KPRED + k] = fbuf[r * 128 + idx] + srecb[idx];
    }
}

// ---------------- launch ------------------------------------------------------
extern "C" void kernel_launch(void* const* d_in, const int* in_sizes, int n_in,
                              void* d_out, int out_size) {
    const int*   item_seq   = (const int*)  d_in[0];
    const int*   items_pred = (const int*)  d_in[1];
    const float* item_emb_w = (const float*)d_in[2];
    const float* rec_emb_w  = (const float*)d_in[3];
    const float* rec_b_w    = (const float*)d_in[4];
    const float* in_proj_w  = (const float*)d_in[5];
    const float* in_proj_b  = (const float*)d_in[6];
    const float* out_proj_w = (const float*)d_in[7];
    const float* out_proj_b = (const float*)d_in[8];
    const float* ln1_g      = (const float*)d_in[9];
    const float* ln1_b      = (const float*)d_in[10];
    const float* ln2_g      = (const float*)d_in[11];
    const float* ln2_b      = (const float*)d_in[12];
    const float* ffn_w1     = (const float*)d_in[13];
    const float* ffn_b1     = (const float*)d_in[14];
    const float* ffn_w2     = (const float*)d_in[15];
    const float* ffn_b2     = (const float*)d_in[16];
    float* out = (float*)d_out;

    int B = in_sizes[0] / SEQ_L;

    cudaFuncSetAttribute(attn_ln1_tc,  cudaFuncAttributeMaxDynamicSharedMemorySize, F_SMEM);
    cudaFuncSetAttribute(ln2_score_tc, cudaFuncAttributeMaxDynamicSharedMemorySize, F_SMEM);
    cudaFuncSetAttribute(gemm1_mma, cudaFuncAttributeMaxDynamicSharedMemorySize, G1_SMEM);
    cudaFuncSetAttribute(gemm2_mma, cudaFuncAttributeMaxDynamicSharedMemorySize, G2_SMEM);

    prep_all<<<2176, 256>>>(in_proj_w, in_proj_b, out_proj_w, out_proj_b,
                            rec_emb_w, ffn_w1, ffn_w2);
    embed_sum<<<B, 128>>>(item_seq, item_emb_w);
    attn_ln1_tc<<<B / 128, 256, F_SMEM>>>(ln1_g, ln1_b);
    gemm1_mma<<<dim3(B / 128, FFDIM / 128), 256, G1_SMEM>>>(ffn_b1);
    gemm2_mma<<<B / 128, 256, G2_SMEM>>>(ffn_b2);
    ln2_score_tc<<<B / 128, 256, F_SMEM>>>(ln2_g, ln2_b, items_pred, rec_b_w, out);
}

// round 8
// speedup vs baseline: 1.5207x; 1.0522x over previous
#include <cuda_runtime.h>
#include <cuda_fp16.h>
#include <cstdint>

#define SEQ_L 50
#define DIM 100
#define KPAD 128
#define FFDIM 2048
#define KPRED 100
#define EPS 1e-5f
#define BMAX 16384

typedef __half fp16;

// ---------------- scratch (device globals) ---------------------------------
__device__ float g_x  [BMAX * DIM];                   // embedding sums
__device__ float g_x1 [BMAX * KPAD];                  // LN1 out fp32 (residual)
__device__ float g_ff [BMAX * DIM];
__device__ float g_c  [KPAD];
__device__ fp16  g_Mf  [KPAD * KPAD];                 // attn matrix fp16
__device__ fp16  g_recf[KPAD * KPAD];                 // rec_emb fp16
__device__ fp16  g_x1f[BMAX * KPAD];                  // LN1 out fp16 (MMA operand)
__device__ fp16  g_w1f[FFDIM * KPAD];
__device__ fp16  g_hf [(size_t)BMAX * FFDIM];         // hidden fp16
__device__ fp16  g_w2f[KPAD * FFDIM];

// ---------------- helpers ----------------------------------------------------
__device__ __forceinline__ uint32_t smem_u32(const void* p) {
    uint32_t a;
    asm("{ .reg .u64 t; cvta.to.shared.u64 t, %1; cvt.u32.u64 %0, t; }" : "=r"(a) : "l"(p));
    return a;
}
__device__ __forceinline__ void ldsm_x4(uint32_t addr, uint32_t& r0, uint32_t& r1,
                                        uint32_t& r2, uint32_t& r3) {
    asm volatile("ldmatrix.sync.aligned.m8n8.x4.shared.b16 {%0,%1,%2,%3}, [%4];"
                 : "=r"(r0), "=r"(r1), "=r"(r2), "=r"(r3) : "r"(addr));
}
__device__ __forceinline__ void mma_f16(float* d, const uint32_t* a, const uint32_t* b) {
    asm volatile("mma.sync.aligned.m16n8k16.row.col.f32.f16.f16.f32 "
                 "{%0,%1,%2,%3}, {%4,%5,%6,%7}, {%8,%9}, {%0,%1,%2,%3};"
                 : "+f"(d[0]), "+f"(d[1]), "+f"(d[2]), "+f"(d[3])
                 : "r"(a[0]), "r"(a[1]), "r"(a[2]), "r"(a[3]), "r"(b[0]), "r"(b[1]));
}
__device__ __forceinline__ void cp16(uint32_t saddr, const void* g) {
    asm volatile("cp.async.cg.shared.global [%0], [%1], 16;" :: "r"(saddr), "l"(g));
}
#define CP_COMMIT() asm volatile("cp.async.commit_group;" ::: "memory")
template<int N> __device__ __forceinline__ void cp_wait() {
    asm volatile("cp.async.wait_group %0;" :: "n"(N) : "memory");
}

// 128x128 warp-tiled MMA phase (8 warps, warp tile 32x64)
template<int AS, int NKS>
__device__ __forceinline__ void mma_tile1(uint32_t sb, uint32_t oA, uint32_t oB,
                                          float acc[2][8][4], int wid, int lid) {
    int wm = wid >> 1, wn = wid & 1;
    int arow = wm * 32, brow = wn * 64;
    int lr = lid & 15, lc8 = (lid >> 4) << 3;
    #pragma unroll
    for (int ks = 0; ks < NKS; ks++) {
        int k0 = ks * 16;
        uint32_t a[2][4];
        #pragma unroll
        for (int mi = 0; mi < 2; mi++) {
            uint32_t off = (uint32_t)(((arow + mi * 16 + lr) * AS + k0 + lc8) * 2);
            ldsm_x4(sb + oA + off, a[mi][0], a[mi][1], a[mi][2], a[mi][3]);
        }
        uint32_t b[8][2];
        #pragma unroll
        for (int nj = 0; nj < 4; nj++) {
            uint32_t off = (uint32_t)(((brow + nj * 16 + lr) * AS + k0 + lc8) * 2);
            uint32_t r0, r1, r2, r3;
            ldsm_x4(sb + oB + off, r0, r1, r2, r3);
            b[nj * 2][0] = r0; b[nj * 2 + 1][0] = r1;
            b[nj * 2][1] = r2; b[nj * 2 + 1][1] = r3;
        }
        #pragma unroll
        for (int mi = 0; mi < 2; mi++)
            #pragma unroll
            for (int n = 0; n < 8; n++)
                mma_f16(acc[mi][n], a[mi], b[n]);
    }
}

// 64x128 warp-tiled MMA phase (8 warps, warp tile 32x32) — for gemm2
template<int AS, int NKS>
__device__ __forceinline__ void mma_tile64(uint32_t sb, uint32_t oA, uint32_t oB,
                                           float acc[2][4][4], int wid, int lid) {
    int wm = wid >> 2, wn = wid & 3;
    int arow = wm * 32, brow = wn * 32;
    int lr = lid & 15, lc8 = (lid >> 4) << 3;
    #pragma unroll
    for (int ks = 0; ks < NKS; ks++) {
        int k0 = ks * 16;
        uint32_t a[2][4];
        #pragma unroll
        for (int mi = 0; mi < 2; mi++) {
            uint32_t off = (uint32_t)(((arow + mi * 16 + lr) * AS + k0 + lc8) * 2);
            ldsm_x4(sb + oA + off, a[mi][0], a[mi][1], a[mi][2], a[mi][3]);
        }
        uint32_t b[4][2];
        #pragma unroll
        for (int nj = 0; nj < 2; nj++) {
            uint32_t off = (uint32_t)(((brow + nj * 16 + lr) * AS + k0 + lc8) * 2);
            uint32_t r0, r1, r2, r3;
            ldsm_x4(sb + oB + off, r0, r1, r2, r3);
            b[nj * 2][0] = r0; b[nj * 2 + 1][0] = r1;
            b[nj * 2][1] = r2; b[nj * 2 + 1][1] = r3;
        }
        #pragma unroll
        for (int mi = 0; mi < 2; mi++)
            #pragma unroll
            for (int n = 0; n < 4; n++)
                mma_f16(acc[mi][n], a[mi], b[n]);
    }
}

// ---------------- K0: fused prep ---------------------------------------------
__global__ void prep_all(const float* __restrict__ in_proj_w,
                         const float* __restrict__ in_proj_b,
                         const float* __restrict__ out_proj_w,
                         const float* __restrict__ out_proj_b,
                         const float* __restrict__ rec_emb,
                         const float* __restrict__ w1,
                         const float* __restrict__ w2) {
    int bid = blockIdx.x, tid = threadIdx.x;
    if (bid < 64) {
        int i = bid * 2 + (tid >> 7);
        int j = tid & 127;
        const float* Wv = in_proj_w + 2 * DIM * DIM;
        const float* bv = in_proj_b + 2 * DIM;
        float mv = 0.f;
        if (i < DIM && j < DIM) {
            #pragma unroll 4
            for (int k = 0; k < DIM; k++)
                mv += out_proj_w[i * DIM + k] * Wv[k * DIM + j];
        }
        g_Mf[i * KPAD + j] = __float2half_rn(mv);
        if (j == 0) {
            float s = 0.f;
            if (i < DIM) {
                s = out_proj_b[i];
                for (int k = 0; k < DIM; k++)
                    s += out_proj_w[i * DIM + k] * bv[k];
            }
            g_c[i] = s;
        }
    } else if (bid < 128) {
        int idx = (bid - 64) * 256 + tid;
        int n = idx >> 7, k = idx & 127;
        float v = (n < DIM && k < DIM) ? rec_emb[n * DIM + k] : 0.f;
        g_recf[idx] = __float2half_rn(v);
    } else if (bid < 128 + 1024) {
        int idx = (bid - 128) * 256 + tid;
        int n = idx >> 7, k = idx & 127;
        float v = (k < DIM) ? w1[n * DIM + k] : 0.f;
        g_w1f[idx] = __float2half_rn(v);
    } else {
        int idx = (bid - 1152) * 256 + tid;
        int n = idx >> 11, k = idx & 2047;
        float v = (n < DIM) ? w2[n * FFDIM + k] : 0.f;
        g_w2f[idx] = __float2half_rn(v);
    }
}

// ---------------- K1: embedding gather-sum ----------------------------------
__global__ void embed_sum(const int* __restrict__ seq,
                          const float* __restrict__ emb) {
    int b = blockIdx.x;
    __shared__ int s_idx[SEQ_L];
    int t = threadIdx.x;
    if (t < SEQ_L) s_idx[t] = seq[b * SEQ_L + t];
    __syncthreads();
    if (t < DIM) {
        float acc = 0.f;
        #pragma unroll 5
        for (int l = 0; l < SEQ_L; l++)
            acc += emb[(size_t)s_idx[l] * DIM + t];
        g_x[b * DIM + t] = acc;
    }
}

// ---------------- fused-tile smem layout (attn_ln1 / ln2_score) -------------
// two fp16 planes (A,B) + 512B tail; fp32 staging overlays A+B after MMA.
#define FAS 136
#define PL_SZ (128 * FAS * 2)          // 34816
#define F_A  0
#define F_B  PL_SZ
#define F_T  (2 * PL_SZ)               // tail vector (cvec / rec_b)
#define F_SMEM (2 * PL_SZ + 512)       // 70144 -> occ 2

// ---------------- K2: fused attn + LN1 --------------------------------------
__global__ __launch_bounds__(256, 2)
void attn_ln1_tc(const float* __restrict__ ln1_g, const float* __restrict__ ln1_b) {
    extern __shared__ char smem[];
    uint32_t sb = smem_u32(smem);
    int tid = threadIdx.x, wid = tid >> 5, lid = tid & 31;
    int m0 = blockIdx.x * 128;
    float* cvec = (float*)(smem + F_T);
    if (tid < KPAD) cvec[tid] = g_c[tid];

    // A plane: fp16 of x (padded)
    for (int idx = tid; idx < 128 * 128; idx += 256) {
        int r = idx >> 7, j = idx & 127;
        float v = (j < DIM) ? g_x[(size_t)(m0 + r) * DIM + j] : 0.f;
        *(fp16*)(smem + F_A + ((r * FAS + j) << 1)) = __float2half_rn(v);
    }
    const uint4* B4 = (const uint4*)g_Mf;
    #pragma unroll
    for (int i = 0; i < 8; i++) {
        int idx = tid + i * 256;
        int r = idx >> 4, c = idx & 15;
        uint32_t so = (uint32_t)((r * FAS + c * 8) * 2);
        *(uint4*)(smem + F_B + so) = B4[r * 16 + c];
    }
    __syncthreads();

    float acc[2][8][4] = {};
    mma_tile1<FAS, 8>(sb, F_A, F_B, acc, wid, lid);
    __syncthreads();

    // overlay: y = x + attn + c staged fp32 over dead A/B planes (stride 132)
    float* ybuf = (float*)smem;
    int wm = wid >> 1, wn = wid & 1;
    int arow = wm * 32, brow = wn * 64;
    #pragma unroll
    for (int mi = 0; mi < 2; mi++)
        #pragma unroll
        for (int n = 0; n < 8; n++) {
            int r = arow + mi * 16 + (lid >> 2);
            int c = brow + n * 8 + (lid & 3) * 2;
            float x0 = (c     < DIM) ? g_x[(size_t)(m0 + r) * DIM + c]     : 0.f;
            float x1v= (c + 1 < DIM) ? g_x[(size_t)(m0 + r) * DIM + c + 1] : 0.f;
            float x2 = (c     < DIM) ? g_x[(size_t)(m0 + r + 8) * DIM + c]     : 0.f;
            float x3 = (c + 1 < DIM) ? g_x[(size_t)(m0 + r + 8) * DIM + c + 1] : 0.f;
            ybuf[r * 132 + c]           = acc[mi][n][0] + x0  + cvec[c];
            ybuf[r * 132 + c + 1]       = acc[mi][n][1] + x1v + cvec[c + 1];
            ybuf[(r + 8) * 132 + c]     = acc[mi][n][2] + x2  + cvec[c];
            ybuf[(r + 8) * 132 + c + 1] = acc[mi][n][3] + x3  + cvec[c + 1];
        }
    __syncthreads();

    for (int rr = 0; rr < 16; rr++) {
        int r = wid * 16 + rr;
        float v[4], s = 0.f, sq = 0.f;
        #pragma unroll
        for (int q = 0; q < 4; q++) {
            int t = lid + q * 32;
            v[q] = (t < DIM) ? ybuf[r * 132 + t] : 0.f;
            s += v[q]; sq += v[q] * v[q];
        }
        #pragma unroll
        for (int off = 16; off; off >>= 1) {
            s  += __shfl_xor_sync(0xffffffffu, s,  off);
            sq += __shfl_xor_sync(0xffffffffu, sq, off);
        }
        float m = s / DIM;
        float inv = rsqrtf(sq / DIM - m * m + EPS);
        #pragma unroll
        for (int q = 0; q < 4; q++) {
            int t = lid + q * 32;
            float o = (t < DIM) ? (v[q] - m) * inv * ln1_g[t] + ln1_b[t] : 0.f;
            g_x1 [(size_t)(m0 + r) * KPAD + t] = o;
            g_x1f[(size_t)(m0 + r) * KPAD + t] = __float2half_rn(o);
        }
    }
}

// ---------------- K3: GEMM1: h = relu(x1 @ W1^T + b1), two K=64 phases -------
#define AS1 72
#define P1SZ (128 * AS1 * 2)           // 18432
#define S1_A  0
#define S1_B  P1SZ
#define S1_BIAS (2 * P1SZ)             // 36864
#define G1_SMEM (2 * P1SZ + 512)

__global__ __launch_bounds__(256, 2)
void gemm1_mma(const float* __restrict__ b1) {
    extern __shared__ char smem[];
    uint32_t sb = smem_u32(smem);
    int tid = threadIdx.x, wid = tid >> 5, lid = tid & 31;
    int m0 = blockIdx.x * 128, n0 = blockIdx.y * 128;
    float* bias = (float*)(smem + S1_BIAS);
    if (tid < 128) bias[tid] = b1[n0 + tid];

    const uint4* A4 = (const uint4*)g_x1f + (size_t)m0 * 16;
    const uint4* B4 = (const uint4*)g_w1f + (size_t)n0 * 16;

    float acc[2][8][4] = {};
    #pragma unroll
    for (int kh = 0; kh < 2; kh++) {
        #pragma unroll
        for (int i = 0; i < 4; i++) {
            int idx = tid + i * 256;
            int r = idx >> 3, c = idx & 7;
            uint32_t so = (uint32_t)((r * AS1 + c * 8) * 2);
            int gc = kh * 8 + c;
            *(uint4*)(smem + S1_A + so) = A4[r * 16 + gc];
            *(uint4*)(smem + S1_B + so) = B4[r * 16 + gc];
        }
        __syncthreads();
        mma_tile1<AS1, 4>(sb, S1_A, S1_B, acc, wid, lid);
        __syncthreads();
    }

    int wm = wid >> 1, wn = wid & 1;
    int arow = wm * 32, brow = wn * 64;
    fp16* sh = (fp16*)smem;                 // stride 136 halves
    #pragma unroll
    for (int mi = 0; mi < 2; mi++)
        #pragma unroll
        for (int n = 0; n < 8; n++) {
            int r = arow + mi * 16 + (lid >> 2);
            int c = brow + n * 8 + (lid & 3) * 2;
            sh[r * 136 + c]           = __float2half_rn(fmaxf(acc[mi][n][0] + bias[c], 0.f));
            sh[r * 136 + c + 1]       = __float2half_rn(fmaxf(acc[mi][n][1] + bias[c + 1], 0.f));
            sh[(r + 8) * 136 + c]     = __float2half_rn(fmaxf(acc[mi][n][2] + bias[c], 0.f));
            sh[(r + 8) * 136 + c + 1] = __float2half_rn(fmaxf(acc[mi][n][3] + bias[c + 1], 0.f));
        }
    __syncthreads();
    uint4* HF = (uint4*)g_hf;
    #pragma unroll
    for (int i = 0; i < 8; i++) {
        int idx = tid + i * 256;
        int r = idx >> 4, c = idx & 15;
        uint32_t so = (uint32_t)((r * 136 + c * 8) * 2);
        HF[(size_t)(m0 + r) * 256 + (n0 >> 3) + c] = *(uint4*)(smem + so);
    }
}

// ---------------- K4: GEMM2: M-tile 64 -> 256 CTAs, K=32 double-buffered -----
#define AS2 40
#define ST_A (64 * AS2 * 2)            // 5120
#define ST_B (128 * AS2 * 2)           // 10240
#define BUF2 (ST_A + ST_B)             // 15360 per stage
#define S2_BIAS (2 * BUF2)             // 30720
#define G2_SMEM (2 * BUF2 + 512)

__global__ __launch_bounds__(256, 2)
void gemm2_mma(const float* __restrict__ b2) {
    extern __shared__ char smem[];
    uint32_t sb = smem_u32(smem);
    int tid = threadIdx.x, wid = tid >> 5, lid = tid & 31;
    int m0 = blockIdx.x * 64;
    float* bias = (float*)(smem + S2_BIAS);
    if (tid < 128) bias[tid] = (tid < DIM) ? b2[tid] : 0.f;

    const uint4* srcA = (const uint4*)g_hf + (size_t)m0 * 256;
    const uint4* srcB = (const uint4*)g_w2f;

    auto load_chunk = [&](int c, int buf) {
        uint32_t bb = sb + buf * BUF2;
        {   // A: 64 rows x 4 uint4
            int r = tid >> 2, cc = tid & 3;
            if (tid < 256) {
                uint32_t so = (uint32_t)((r * AS2 + cc * 8) * 2);
                cp16(bb + so, srcA + (size_t)r * 256 + c * 4 + cc);
            }
        }
        #pragma unroll
        for (int i = 0; i < 2; i++) {   // B: 128 rows x 4 uint4
            int idx = tid + i * 256;
            int r = idx >> 2, cc = idx & 3;
            uint32_t so = (uint32_t)((r * AS2 + cc * 8) * 2);
            cp16(bb + ST_A + so, srcB + (size_t)r * 256 + c * 4 + cc);
        }
    };

    float acc[2][4][4] = {};
    load_chunk(0, 0);
    CP_COMMIT();

    for (int c = 0; c < 64; c++) {
        if (c + 1 < 64) {
            load_chunk(c + 1, (c + 1) & 1);
            CP_COMMIT();
            cp_wait<1>();
        } else {
            cp_wait<0>();
        }
        __syncthreads();
        uint32_t bb = sb + (c & 1) * BUF2;
        mma_tile64<AS2, 2>(bb, 0, ST_A, acc, wid, lid);
        __syncthreads();
    }

    int wm = wid >> 2, wn = wid & 3;
    int arow = wm * 32, brow = wn * 32;
    #pragma unroll
    for (int mi = 0; mi < 2; mi++)
        #pragma unroll
        for (int n = 0; n < 4; n++) {
            int gr = m0 + arow + mi * 16 + (lid >> 2);
            int cc = brow + n * 8 + (lid & 3) * 2;
            if (cc < DIM) {
                g_ff[(size_t)gr * DIM + cc]       = acc[mi][n][0] + bias[cc];
                g_ff[(size_t)(gr + 8) * DIM + cc] = acc[mi][n][2] + bias[cc];
            }
            if (cc + 1 < DIM) {
                g_ff[(size_t)gr * DIM + cc + 1]       = acc[mi][n][1] + bias[cc + 1];
                g_ff[(size_t)(gr + 8) * DIM + cc + 1] = acc[mi][n][3] + bias[cc + 1];
            }
        }
}

// ---------------- K5: fused LN2 + scoring ------------------------------------
__global__ __launch_bounds__(256, 2)
void ln2_score_tc(const float* __restrict__ ln2_g, const float* __restrict__ ln2_b,
                  const int* __restrict__ items, const float* __restrict__ rec_b,
                  float* __restrict__ out) {
    extern __shared__ char smem[];
    uint32_t sb = smem_u32(smem);
    int tid = threadIdx.x, wid = tid >> 5, lid = tid & 31;
    int m0 = blockIdx.x * 128;
    float* srecb = (float*)(smem + F_T);
    if (tid < KPAD) srecb[tid] = (tid < DIM) ? rec_b[tid] : 0.f;

    // B plane (rec_emb)
    const uint4* B4 = (const uint4*)g_recf;
    #pragma unroll
    for (int i = 0; i < 8; i++) {
        int idx = tid + i * 256;
        int r = idx >> 4, c = idx & 15;
        uint32_t so = (uint32_t)((r * FAS + c * 8) * 2);
        *(uint4*)(smem + F_B + so) = B4[r * 16 + c];
    }

    // LN per row, reading y = x1 + ff straight from global -> fp16 A plane
    for (int rr = 0; rr < 16; rr++) {
        int r = wid * 16 + rr;
        float v[4], s = 0.f, sq = 0.f;
        #pragma unroll
        for (int q = 0; q < 4; q++) {
            int t = lid + q * 32;
            v[q] = (t < DIM) ? g_x1[(size_t)(m0 + r) * KPAD + t]
                             + g_ff[(size_t)(m0 + r) * DIM + t] : 0.f;
            s += v[q]; sq += v[q] * v[q];
        }
        #pragma unroll
        for (int off = 16; off; off >>= 1) {
            s  += __shfl_xor_sync(0xffffffffu, s,  off);
            sq += __shfl_xor_sync(0xffffffffu, sq, off);
        }
        float m = s / DIM;
        float inv = rsqrtf(sq / DIM - m * m + EPS);
        #pragma unroll
        for (int q = 0; q < 4; q++) {
            int t = lid + q * 32;
            float o = (t < DIM) ? (v[q] - m) * inv * ln2_g[t] + ln2_b[t] : 0.f;
            *(fp16*)(smem + F_A + ((r * FAS + t) << 1)) = __float2half_rn(o);
        }
    }
    __syncthreads();

    float acc[2][8][4] = {};
    mma_tile1<FAS, 8>(sb, F_A, F_B, acc, wid, lid);
    __syncthreads();

    // overlay P fp32 (stride 128) over dead A/B planes
    float* fbuf = (float*)smem;
    int wm = wid >> 1, wn = wid & 1;
    int arow = wm * 32, brow = wn * 64;
    #pragma unroll
    for (int mi = 0; mi < 2; mi++)
        #pragma unroll
        for (int n = 0; n < 8; n++) {
            int r = arow + mi * 16 + (lid >> 2);
            int c = brow + n * 8 + (lid & 3) * 2;
            fbuf[r * 128 + c]           = acc[mi][n][0];
            fbuf[r * 128 + c + 1]       = acc[mi][n][1];
            fbuf[(r + 8) * 128 + c]     = acc[mi][n][2];
            fbuf[(r + 8) * 128 + c + 1] = acc[mi][n][3];
        }
    __syncthreads();

    for (int o = tid; o < 128 * KPRED; o += 256) {
        int r = o / KPRED, k = o - r * KPRED;
        int idx = items[(size_t)(m0 + r) * KPRED + k];
        out[(size_t)(m0 + r) * KPRED + k] = fbuf[r * 128 + idx] + srecb[idx];
    }
}

// ---------------- launch ------------------------------------------------------
extern "C" void kernel_launch(void* const* d_in, const int* in_sizes, int n_in,
                              void* d_out, int out_size) {
    const int*   item_seq   = (const int*)  d_in[0];
    const int*   items_pred = (const int*)  d_in[1];
    const float* item_emb_w = (const float*)d_in[2];
    const float* rec_emb_w  = (const float*)d_in[3];
    const float* rec_b_w    = (const float*)d_in[4];
    const float* in_proj_w  = (const float*)d_in[5];
    const float* in_proj_b  = (const float*)d_in[6];
    const float* out_proj_w = (const float*)d_in[7];
    const float* out_proj_b = (const float*)d_in[8];
    const float* ln1_g      = (const float*)d_in[9];
    const float* ln1_b      = (const float*)d_in[10];
    const float* ln2_g      = (const float*)d_in[11];
    const float* ln2_b      = (const float*)d_in[12];
    const float* ffn_w1     = (const float*)d_in[13];
    const float* ffn_b1     = (const float*)d_in[14];
    const float* ffn_w2     = (const float*)d_in[15];
    const float* ffn_b2     = (const float*)d_in[16];
    float* out = (float*)d_out;

    int B = in_sizes[0] / SEQ_L;

    cudaFuncSetAttribute(attn_ln1_tc,  cudaFuncAttributeMaxDynamicSharedMemorySize, F_SMEM);
    cudaFuncSetAttribute(ln2_score_tc, cudaFuncAttributeMaxDynamicSharedMemorySize, F_SMEM);
    cudaFuncSetAttribute(gemm1_mma, cudaFuncAttributeMaxDynamicSharedMemorySize, G1_SMEM);
    cudaFuncSetAttribute(gemm2_mma, cudaFuncAttributeMaxDynamicSharedMemorySize, G2_SMEM);

    prep_all<<<2176, 256>>>(in_proj_w, in_proj_b, out_proj_w, out_proj_b,
                            rec_emb_w, ffn_w1, ffn_w2);
    embed_sum<<<B, 128>>>(item_seq, item_emb_w);
    attn_ln1_tc<<<B / 128, 256, F_SMEM>>>(ln1_g, ln1_b);
    gemm1_mma<<<dim3(B / 128, FFDIM / 128), 256, G1_SMEM>>>(ffn_b1);
    gemm2_mma<<<B / 64, 256, G2_SMEM>>>(ffn_b2);
    ln2_score_tc<<<B / 128, 256, F_SMEM>>>(ln2_g, ln2_b, items_pred, rec_b_w, out);
}